// round 1
// baseline (speedup 1.0000x reference)
#include <cuda_runtime.h>
#include <cuda_bf16.h>
#include <cstdint>

// Problem constants (shapes are fixed by the reference, but we read runtime
// sizes from in_sizes anyway).
#define HDIM 128
#define MAXN 100000

// Scratch (device globals; no allocation allowed).
__device__ float g_agg[(size_t)MAXN * HDIM];
__device__ float g_z  [(size_t)MAXN * HDIM];
__device__ float g_h0 [(size_t)MAXN * HDIM];
__device__ float g_h1 [(size_t)MAXN * HDIM];

// ---------------------------------------------------------------------------
// Vector atomic add helper (sm_90+ has native float4 atomicAdd)
// ---------------------------------------------------------------------------
__device__ __forceinline__ void atomic_add_f4(float4* addr, float4 v) {
#if __CUDA_ARCH__ >= 900
    atomicAdd(addr, v);
#else
    float* f = (float*)addr;
    atomicAdd(f + 0, v.x);
    atomicAdd(f + 1, v.y);
    atomicAdd(f + 2, v.z);
    atomicAdd(f + 3, v.w);
#endif
}

// ---------------------------------------------------------------------------
// Zero a float buffer (element count divisible by 4)
// ---------------------------------------------------------------------------
__global__ void zero_kernel(float4* __restrict__ p, size_t n4) {
    size_t i = (size_t)blockIdx.x * blockDim.x + threadIdx.x;
    if (i < n4) p[i] = make_float4(0.f, 0.f, 0.f, 0.f);
}

// ---------------------------------------------------------------------------
// Scatter-add: for each edge e, agg[dst[e], :] += h[src[e], :]
// One warp per edge; each lane handles a float4 (32 lanes * 4 = 128 floats).
// ---------------------------------------------------------------------------
__global__ void scatter_kernel(const float* __restrict__ h,
                               const int* __restrict__ src,
                               const int* __restrict__ dst,
                               float* __restrict__ agg,
                               int E) {
    int warp = (int)(((size_t)blockIdx.x * blockDim.x + threadIdx.x) >> 5);
    int lane = threadIdx.x & 31;
    if (warp >= E) return;
    int s = __ldg(&src[warp]);
    int d = __ldg(&dst[warp]);
    const float4* hs = (const float4*)(h + (size_t)s * HDIM);
    float4*       ad = (float4*)(agg + (size_t)d * HDIM);
    float4 v = __ldg(&hs[lane]);
    atomic_add_f4(&ad[lane], v);
}

// ---------------------------------------------------------------------------
// GEMM: C[M,128] = relu( (A (+ A2)) @ W[128,128] + b[128] )
// BM=64, BN=128, BK=32. 256 threads; each computes an 8x4 micro-tile.
// A2 (optional second addend, fused agg + h) may be null.
// ---------------------------------------------------------------------------
__global__ __launch_bounds__(256) void gemm_relu_kernel(
    const float* __restrict__ A,
    const float* __restrict__ A2,          // may be nullptr
    const float* __restrict__ W,           // [128,128] row-major (k, n)
    const float* __restrict__ bias,        // [128]
    float* __restrict__ C,
    int M) {
    __shared__ float As[64][33];           // [row][k], padded
    __shared__ float Ws[32][128];          // [k][n]

    const int tid = threadIdx.x;
    const int tc  = tid & 31;              // col group 0..31 (4 cols each)
    const int tr  = tid >> 5;              // row group 0..7  (8 rows each)
    const int rowBase = blockIdx.x * 64;

    float acc[8][4];
#pragma unroll
    for (int i = 0; i < 8; i++)
#pragma unroll
        for (int j = 0; j < 4; j++) acc[i][j] = 0.f;

    for (int kb = 0; kb < HDIM; kb += 32) {
        // Load A tile (64 rows x 32 k). Thread t loads elements t, t+256, ...
        // i>>5 = row, i&31 = k → warp writes 32 consecutive floats: coalesced
        // gmem read and conflict-free smem write.
#pragma unroll
        for (int i = tid; i < 64 * 32; i += 256) {
            int r = i >> 5;
            int k = i & 31;
            int gr = rowBase + r;
            float v = 0.f;
            if (gr < M) {
                size_t off = (size_t)gr * HDIM + kb + k;
                v = A[off];
                if (A2) v += A2[off];
            }
            As[r][k] = v;
        }
        // Load W chunk (32 k x 128 n)
#pragma unroll
        for (int i = tid; i < 32 * 128; i += 256) {
            int k = i >> 7;
            int n = i & 127;
            Ws[k][n] = W[(size_t)(kb + k) * HDIM + n];
        }
        __syncthreads();

#pragma unroll
        for (int k = 0; k < 32; k++) {
            float a[8], bb[4];
#pragma unroll
            for (int i = 0; i < 8; i++) a[i] = As[tr * 8 + i][k];  // broadcast in-warp
            float4 bv = *(const float4*)&Ws[k][tc * 4];
            bb[0] = bv.x; bb[1] = bv.y; bb[2] = bv.z; bb[3] = bv.w;
#pragma unroll
            for (int i = 0; i < 8; i++)
#pragma unroll
                for (int j = 0; j < 4; j++)
                    acc[i][j] = fmaf(a[i], bb[j], acc[i][j]);
        }
        __syncthreads();
    }

    // Epilogue: bias + relu, vectorized store
    float4 bv = *(const float4*)&bias[tc * 4];
#pragma unroll
    for (int i = 0; i < 8; i++) {
        int gr = rowBase + tr * 8 + i;
        if (gr >= M) continue;
        float4 o;
        o.x = fmaxf(acc[i][0] + bv.x, 0.f);
        o.y = fmaxf(acc[i][1] + bv.y, 0.f);
        o.z = fmaxf(acc[i][2] + bv.z, 0.f);
        o.w = fmaxf(acc[i][3] + bv.w, 0.f);
        *(float4*)&C[(size_t)gr * HDIM + tc * 4] = o;
    }
}

// ---------------------------------------------------------------------------
// Global add pool: out[batch[n], :] += h[n, :]
// One warp per node, float4 atomics.
// ---------------------------------------------------------------------------
__global__ void pool_kernel(const float* __restrict__ h,
                            const int* __restrict__ batch,
                            float* __restrict__ out,
                            int M) {
    int warp = (int)(((size_t)blockIdx.x * blockDim.x + threadIdx.x) >> 5);
    int lane = threadIdx.x & 31;
    if (warp >= M) return;
    int g = __ldg(&batch[warp]);
    float4 v = __ldg(((const float4*)(h + (size_t)warp * HDIM)) + lane);
    atomic_add_f4(((float4*)(out + (size_t)g * HDIM)) + lane, v);
}

// ---------------------------------------------------------------------------
// Launch
// ---------------------------------------------------------------------------
extern "C" void kernel_launch(void* const* d_in, const int* in_sizes, int n_in,
                              void* d_out, int out_size) {
    const float* x     = (const float*)d_in[0];
    const int*   ei    = (const int*)d_in[1];
    const int*   batch = (const int*)d_in[2];
    const float* W1[3] = {(const float*)d_in[3], (const float*)d_in[7],  (const float*)d_in[11]};
    const float* b1[3] = {(const float*)d_in[4], (const float*)d_in[8],  (const float*)d_in[12]};
    const float* W2[3] = {(const float*)d_in[5], (const float*)d_in[9],  (const float*)d_in[13]};
    const float* b2[3] = {(const float*)d_in[6], (const float*)d_in[10], (const float*)d_in[14]};

    const int Nn = in_sizes[0] / HDIM;
    const int Ee = in_sizes[1] / 2;
    const int* src = ei;
    const int* dst = ei + Ee;

    float *agg, *zbuf, *h0, *h1;
    cudaGetSymbolAddress((void**)&agg,  g_agg);
    cudaGetSymbolAddress((void**)&zbuf, g_z);
    cudaGetSymbolAddress((void**)&h0,   g_h0);
    cudaGetSymbolAddress((void**)&h1,   g_h1);
    float* hbuf[2] = {h0, h1};

    const size_t nh  = (size_t)Nn * HDIM;
    const int zb_blocks  = (int)((nh / 4 + 255) / 256);
    const int sc_blocks  = (Ee + 7) / 8;                 // 8 warps per 256-thread block
    const int gm_blocks  = (Nn + 63) / 64;
    const int pool_blocks = (Nn + 7) / 8;

    const float* hin = x;
    for (int layer = 0; layer < 3; layer++) {
        float* hout = hbuf[layer & 1];
        zero_kernel<<<zb_blocks, 256>>>((float4*)agg, nh / 4);
        scatter_kernel<<<sc_blocks, 256>>>(hin, src, dst, agg, Ee);
        gemm_relu_kernel<<<gm_blocks, 256>>>(agg, hin, W1[layer], b1[layer], zbuf, Nn);
        gemm_relu_kernel<<<gm_blocks, 256>>>(zbuf, nullptr, W2[layer], b2[layer], hout, Nn);
        hin = hout;
    }

    float* out = (float*)d_out;
    const int zo_blocks = (out_size / 4 + 255) / 256;
    zero_kernel<<<zo_blocks, 256>>>((float4*)out, out_size / 4);
    pool_kernel<<<pool_blocks, 256>>>(hin, batch, out, Nn);
}

// round 3
// speedup vs baseline: 1.4306x; 1.4306x over previous
#include <cuda_runtime.h>
#include <cuda_bf16.h>
#include <cstdint>

#define HDIM 128
#define MAXN 100000

// Scratch (device globals; no allocation allowed).
__device__ float g_agg[(size_t)MAXN * HDIM];
__device__ float g_z  [(size_t)MAXN * HDIM];
__device__ float g_h0 [(size_t)MAXN * HDIM];
__device__ float g_h1 [(size_t)MAXN * HDIM];

// ---------------------------------------------------------------------------
// Helpers
// ---------------------------------------------------------------------------
__device__ __forceinline__ void atomic_add_f4(float4* addr, float4 v) {
#if __CUDA_ARCH__ >= 900
    atomicAdd(addr, v);
#else
    float* f = (float*)addr;
    atomicAdd(f + 0, v.x); atomicAdd(f + 1, v.y);
    atomicAdd(f + 2, v.z); atomicAdd(f + 3, v.w);
#endif
}

// tf32 lives in a b32 register in PTX — destination must be "=r", not "=f".
__device__ __forceinline__ uint32_t to_tf32(float x) {
    uint32_t r;
    asm("cvt.rna.tf32.f32 %0, %1;" : "=r"(r) : "f"(x));
    return r;
}

__device__ __forceinline__ void mma_tf32(float d[4],
                                         uint32_t a0, uint32_t a1, uint32_t a2, uint32_t a3,
                                         uint32_t b0, uint32_t b1) {
    asm volatile(
        "mma.sync.aligned.m16n8k8.row.col.f32.tf32.tf32.f32 "
        "{%0,%1,%2,%3}, {%4,%5,%6,%7}, {%8,%9}, {%0,%1,%2,%3};\n"
        : "+f"(d[0]), "+f"(d[1]), "+f"(d[2]), "+f"(d[3])
        : "r"(a0), "r"(a1), "r"(a2), "r"(a3), "r"(b0), "r"(b1));
}

// ---------------------------------------------------------------------------
// Utility kernels
// ---------------------------------------------------------------------------
__global__ void zero_kernel(float4* __restrict__ p, size_t n4) {
    size_t i = (size_t)blockIdx.x * blockDim.x + threadIdx.x;
    if (i < n4) p[i] = make_float4(0.f, 0.f, 0.f, 0.f);
}

__global__ void copy_kernel(float4* __restrict__ dst, const float4* __restrict__ src, size_t n4) {
    size_t i = (size_t)blockIdx.x * blockDim.x + threadIdx.x;
    if (i < n4) dst[i] = src[i];
}

// ---------------------------------------------------------------------------
// Scatter-add: agg[dst[e], :] += h[src[e], :] (agg pre-initialized to h)
// One warp per edge; each lane handles a float4.
// ---------------------------------------------------------------------------
__global__ void scatter_kernel(const float* __restrict__ h,
                               const int* __restrict__ src,
                               const int* __restrict__ dst,
                               float* __restrict__ agg,
                               int E) {
    int warp = (int)(((size_t)blockIdx.x * blockDim.x + threadIdx.x) >> 5);
    int lane = threadIdx.x & 31;
    if (warp >= E) return;
    int s = __ldg(&src[warp]);
    int d = __ldg(&dst[warp]);
    const float4* hs = (const float4*)(h + (size_t)s * HDIM);
    float4*       ad = (float4*)(agg + (size_t)d * HDIM);
    float4 v = __ldg(&hs[lane]);
    atomic_add_f4(&ad[lane], v);
}

// ---------------------------------------------------------------------------
// Tensor-core GEMM: C[M,128] = relu( A @ W[128,128] + b )  via tf32 mma.sync
// BM=128, BN=128, K chunked by 32. 256 threads = 8 warps (4 x M, 2 x N),
// each warp computes a 32x64 tile as 2 m-tiles x 8 n-tiles of m16n8k8.
// ---------------------------------------------------------------------------
__global__ __launch_bounds__(256) void gemm_tc_kernel(
    const float* __restrict__ A,
    const float* __restrict__ W,      // [128,128] row-major (k, n)
    const float* __restrict__ bias,   // [128]
    float* __restrict__ C,
    int M) {
    __shared__ uint32_t As[128][36];  // 128 rows x 32 k (tf32 bits; pad -> conflict-free)
    __shared__ uint32_t Ws[32][132];  // 32 k x 128 n   (tf32 bits; pad -> conflict-free)

    const int tid  = threadIdx.x;
    const int lane = tid & 31;
    const int wid  = tid >> 5;
    const int warp_m = (wid & 3) * 32;   // 4 warps along M
    const int warp_n = (wid >> 2) * 64;  // 2 warps along N
    const int g = lane >> 2;             // 0..7
    const int c = lane & 3;              // 0..3
    const int rowBase = blockIdx.x * 128;

    float acc[2][8][4];
#pragma unroll
    for (int mt = 0; mt < 2; mt++)
#pragma unroll
        for (int nt = 0; nt < 8; nt++)
#pragma unroll
            for (int j = 0; j < 4; j++) acc[mt][nt][j] = 0.f;

    for (int kc = 0; kc < HDIM; kc += 32) {
        // Load A chunk: 128 rows x 32 k (1024 float4, 4 per thread), convert tf32
#pragma unroll
        for (int i = tid; i < 128 * 8; i += 256) {
            int r  = i >> 3;
            int c4 = (i & 7) * 4;
            int gr = rowBase + r;
            float4 v = make_float4(0.f, 0.f, 0.f, 0.f);
            if (gr < M) v = *(const float4*)&A[(size_t)gr * HDIM + kc + c4];
            As[r][c4 + 0] = to_tf32(v.x);
            As[r][c4 + 1] = to_tf32(v.y);
            As[r][c4 + 2] = to_tf32(v.z);
            As[r][c4 + 3] = to_tf32(v.w);
        }
        // Load W chunk: 32 k x 128 n
#pragma unroll
        for (int i = tid; i < 32 * 32; i += 256) {
            int r  = i >> 5;
            int c4 = (i & 31) * 4;
            float4 v = *(const float4*)&W[(size_t)(kc + r) * HDIM + c4];
            Ws[r][c4 + 0] = to_tf32(v.x);
            Ws[r][c4 + 1] = to_tf32(v.y);
            Ws[r][c4 + 2] = to_tf32(v.z);
            Ws[r][c4 + 3] = to_tf32(v.w);
        }
        __syncthreads();

#pragma unroll
        for (int ks = 0; ks < 4; ks++) {
            const int k0 = ks * 8;
            uint32_t a[2][4];
#pragma unroll
            for (int mt = 0; mt < 2; mt++) {
                int rb = warp_m + mt * 16;
                a[mt][0] = As[rb + g    ][k0 + c    ];
                a[mt][1] = As[rb + 8 + g][k0 + c    ];
                a[mt][2] = As[rb + g    ][k0 + c + 4];
                a[mt][3] = As[rb + 8 + g][k0 + c + 4];
            }
#pragma unroll
            for (int nt = 0; nt < 8; nt++) {
                int n = warp_n + nt * 8 + g;
                uint32_t b0 = Ws[k0 + c    ][n];
                uint32_t b1 = Ws[k0 + 4 + c][n];
#pragma unroll
                for (int mt = 0; mt < 2; mt++)
                    mma_tf32(acc[mt][nt], a[mt][0], a[mt][1], a[mt][2], a[mt][3], b0, b1);
            }
        }
        __syncthreads();
    }

    // Epilogue: bias + relu, store float2 pairs per fragment
#pragma unroll
    for (int nt = 0; nt < 8; nt++) {
        int col = warp_n + nt * 8 + 2 * c;
        float2 bb = *(const float2*)&bias[col];
#pragma unroll
        for (int mt = 0; mt < 2; mt++) {
            int row0 = rowBase + warp_m + mt * 16 + g;
            int row1 = row0 + 8;
            if (row0 < M) {
                float2 o;
                o.x = fmaxf(acc[mt][nt][0] + bb.x, 0.f);
                o.y = fmaxf(acc[mt][nt][1] + bb.y, 0.f);
                *(float2*)&C[(size_t)row0 * HDIM + col] = o;
            }
            if (row1 < M) {
                float2 o;
                o.x = fmaxf(acc[mt][nt][2] + bb.x, 0.f);
                o.y = fmaxf(acc[mt][nt][3] + bb.y, 0.f);
                *(float2*)&C[(size_t)row1 * HDIM + col] = o;
            }
        }
    }
}

// ---------------------------------------------------------------------------
// Global add pool: out[batch[n], :] += h[n, :]
// ---------------------------------------------------------------------------
__global__ void pool_kernel(const float* __restrict__ h,
                            const int* __restrict__ batch,
                            float* __restrict__ out,
                            int M) {
    int warp = (int)(((size_t)blockIdx.x * blockDim.x + threadIdx.x) >> 5);
    int lane = threadIdx.x & 31;
    if (warp >= M) return;
    int g = __ldg(&batch[warp]);
    float4 v = __ldg(((const float4*)(h + (size_t)warp * HDIM)) + lane);
    atomic_add_f4(((float4*)(out + (size_t)g * HDIM)) + lane, v);
}

// ---------------------------------------------------------------------------
// Launch
// ---------------------------------------------------------------------------
extern "C" void kernel_launch(void* const* d_in, const int* in_sizes, int n_in,
                              void* d_out, int out_size) {
    const float* x     = (const float*)d_in[0];
    const int*   ei    = (const int*)d_in[1];
    const int*   batch = (const int*)d_in[2];
    const float* W1[3] = {(const float*)d_in[3], (const float*)d_in[7],  (const float*)d_in[11]};
    const float* b1[3] = {(const float*)d_in[4], (const float*)d_in[8],  (const float*)d_in[12]};
    const float* W2[3] = {(const float*)d_in[5], (const float*)d_in[9],  (const float*)d_in[13]};
    const float* b2[3] = {(const float*)d_in[6], (const float*)d_in[10], (const float*)d_in[14]};

    const int Nn = in_sizes[0] / HDIM;
    const int Ee = in_sizes[1] / 2;
    const int* src = ei;
    const int* dst = ei + Ee;

    float *agg, *zbuf, *h0, *h1;
    cudaGetSymbolAddress((void**)&agg,  g_agg);
    cudaGetSymbolAddress((void**)&zbuf, g_z);
    cudaGetSymbolAddress((void**)&h0,   g_h0);
    cudaGetSymbolAddress((void**)&h1,   g_h1);
    float* hbuf[2] = {h0, h1};

    const size_t nh = (size_t)Nn * HDIM;
    const int cp_blocks   = (int)((nh / 4 + 255) / 256);
    const int sc_blocks   = (Ee + 7) / 8;
    const int gm_blocks   = (Nn + 127) / 128;
    const int pool_blocks = (Nn + 7) / 8;

    const float* hin = x;
    for (int layer = 0; layer < 3; layer++) {
        float* hout = hbuf[layer & 1];
        // agg = h (self term), then scatter-add neighbor messages
        copy_kernel<<<cp_blocks, 256>>>((float4*)agg, (const float4*)hin, nh / 4);
        scatter_kernel<<<sc_blocks, 256>>>(hin, src, dst, agg, Ee);
        gemm_tc_kernel<<<gm_blocks, 256>>>(agg,  W1[layer], b1[layer], zbuf, Nn);
        gemm_tc_kernel<<<gm_blocks, 256>>>(zbuf, W2[layer], b2[layer], hout, Nn);
        hin = hout;
    }

    float* out = (float*)d_out;
    const int zo_blocks = (out_size / 4 + 255) / 256;
    zero_kernel<<<zo_blocks, 256>>>((float4*)out, out_size / 4);
    pool_kernel<<<pool_blocks, 256>>>(hin, batch, out, Nn);
}

// round 5
// speedup vs baseline: 2.1149x; 1.4784x over previous
#include <cuda_runtime.h>
#include <cuda_bf16.h>
#include <cstdint>

#define HDIM 128
#define MAXN 100000
#define MAXE 1600000

// Scratch (device globals; no allocation allowed).
__device__ float g_agg[(size_t)MAXN * HDIM];
__device__ float g_z  [(size_t)MAXN * HDIM];
__device__ float g_h0 [(size_t)MAXN * HDIM];
__device__ float g_h1 [(size_t)MAXN * HDIM];
__device__ int   g_offs[MAXN + 1];
__device__ int   g_cursor[MAXN];     // count -> cursor (reused)
__device__ int   g_ssrc[MAXE];       // src ids sorted by dst

// ---------------------------------------------------------------------------
// Helpers
// ---------------------------------------------------------------------------
__device__ __forceinline__ void atomic_add_f4(float4* addr, float4 v) {
#if __CUDA_ARCH__ >= 900
    atomicAdd(addr, v);
#else
    float* f = (float*)addr;
    atomicAdd(f + 0, v.x); atomicAdd(f + 1, v.y);
    atomicAdd(f + 2, v.z); atomicAdd(f + 3, v.w);
#endif
}

__device__ __forceinline__ uint32_t to_tf32(float x) {
    uint32_t r;
    asm("cvt.rna.tf32.f32 %0, %1;" : "=r"(r) : "f"(x));
    return r;
}

__device__ __forceinline__ void mma_tf32(float d[4],
                                         uint32_t a0, uint32_t a1, uint32_t a2, uint32_t a3,
                                         uint32_t b0, uint32_t b1) {
    asm volatile(
        "mma.sync.aligned.m16n8k8.row.col.f32.tf32.tf32.f32 "
        "{%0,%1,%2,%3}, {%4,%5,%6,%7}, {%8,%9}, {%0,%1,%2,%3};\n"
        : "+f"(d[0]), "+f"(d[1]), "+f"(d[2]), "+f"(d[3])
        : "r"(a0), "r"(a1), "r"(a2), "r"(a3), "r"(b0), "r"(b1));
}

// ---------------------------------------------------------------------------
// CSR build kernels
// ---------------------------------------------------------------------------
__global__ void zero_int_kernel(int* __restrict__ p, int n) {
    int i = blockIdx.x * blockDim.x + threadIdx.x;
    if (i < n) p[i] = 0;
}

__global__ void hist_kernel(const int* __restrict__ dst, int* __restrict__ count, int E) {
    int e = blockIdx.x * blockDim.x + threadIdx.x;
    if (e < E) atomicAdd(&count[__ldg(&dst[e])], 1);
}

// Single-block exclusive scan over N counts. cnt is read as counts and
// overwritten with the exclusive prefix (cursor init). offs gets the same
// prefix plus offs[N] = total.
__global__ __launch_bounds__(1024) void scan_kernel(int* __restrict__ cnt,
                                                    int* __restrict__ offs,
                                                    int N, int C) {
    __shared__ int part[1024];
    const int t = threadIdx.x;
    const int beg = min(t * C, N);
    const int end = min(beg + C, N);
    int s = 0;
    for (int i = beg; i < end; i++) s += cnt[i];
    part[t] = s;
    __syncthreads();
    // inclusive scan (Hillis-Steele)
    for (int d = 1; d < 1024; d <<= 1) {
        int val = (t >= d) ? part[t - d] : 0;
        __syncthreads();
        if (t >= d) part[t] += val;
        __syncthreads();
    }
    int run = (t == 0) ? 0 : part[t - 1];
    for (int i = beg; i < end; i++) {
        int c = cnt[i];
        offs[i] = run;
        cnt[i]  = run;   // cursor start
        run += c;
    }
    if (t == 1023) offs[N] = part[1023];
}

__global__ void permute_kernel(const int* __restrict__ src,
                               const int* __restrict__ dst,
                               int* __restrict__ cursor,
                               int* __restrict__ ssrc, int E) {
    int e = blockIdx.x * blockDim.x + threadIdx.x;
    if (e >= E) return;
    int d = __ldg(&dst[e]);
    int pos = atomicAdd(&cursor[d], 1);
    ssrc[pos] = __ldg(&src[e]);
}

// ---------------------------------------------------------------------------
// Gather: agg[n,:] = h[n,:] + sum_{e: dst==n} h[src[e],:]
// One warp per node; lane handles a float4 (32*4 = 128). No atomics.
// ---------------------------------------------------------------------------
__global__ __launch_bounds__(256) void gather_kernel(const float* __restrict__ h,
                                                     const int* __restrict__ ssrc,
                                                     const int* __restrict__ offs,
                                                     float* __restrict__ agg,
                                                     int N) {
    int node = (int)(((size_t)blockIdx.x * blockDim.x + threadIdx.x) >> 5);
    int lane = threadIdx.x & 31;
    if (node >= N) return;
    const float4* hb = (const float4*)h;
    int beg = __ldg(&offs[node]);
    int end = __ldg(&offs[node + 1]);

    float4 v0 = __ldg(hb + (size_t)node * 32 + lane);   // self term
    float4 v1 = make_float4(0.f, 0.f, 0.f, 0.f);
    int i = beg;
    for (; i + 1 < end; i += 2) {
        int s0 = __ldg(&ssrc[i]);
        int s1 = __ldg(&ssrc[i + 1]);
        float4 a = __ldg(hb + (size_t)s0 * 32 + lane);
        float4 b = __ldg(hb + (size_t)s1 * 32 + lane);
        v0.x += a.x; v0.y += a.y; v0.z += a.z; v0.w += a.w;
        v1.x += b.x; v1.y += b.y; v1.z += b.z; v1.w += b.w;
    }
    if (i < end) {
        int s0 = __ldg(&ssrc[i]);
        float4 a = __ldg(hb + (size_t)s0 * 32 + lane);
        v0.x += a.x; v0.y += a.y; v0.z += a.z; v0.w += a.w;
    }
    v0.x += v1.x; v0.y += v1.y; v0.z += v1.z; v0.w += v1.w;
    ((float4*)agg)[(size_t)node * 32 + lane] = v0;
}

// ---------------------------------------------------------------------------
// Tensor-core GEMM: C[M,128] = relu( A @ W[128,128] + b )  via tf32 mma.sync
// ---------------------------------------------------------------------------
__global__ __launch_bounds__(256) void gemm_tc_kernel(
    const float* __restrict__ A,
    const float* __restrict__ W,
    const float* __restrict__ bias,
    float* __restrict__ C,
    int M) {
    __shared__ uint32_t As[128][36];
    __shared__ uint32_t Ws[32][132];

    const int tid  = threadIdx.x;
    const int lane = tid & 31;
    const int wid  = tid >> 5;
    const int warp_m = (wid & 3) * 32;
    const int warp_n = (wid >> 2) * 64;
    const int g = lane >> 2;
    const int c = lane & 3;
    const int rowBase = blockIdx.x * 128;

    float acc[2][8][4];
#pragma unroll
    for (int mt = 0; mt < 2; mt++)
#pragma unroll
        for (int nt = 0; nt < 8; nt++)
#pragma unroll
            for (int j = 0; j < 4; j++) acc[mt][nt][j] = 0.f;

    for (int kc = 0; kc < HDIM; kc += 32) {
#pragma unroll
        for (int i = tid; i < 128 * 8; i += 256) {
            int r  = i >> 3;
            int c4 = (i & 7) * 4;
            int gr = rowBase + r;
            float4 v = make_float4(0.f, 0.f, 0.f, 0.f);
            if (gr < M) v = *(const float4*)&A[(size_t)gr * HDIM + kc + c4];
            As[r][c4 + 0] = to_tf32(v.x);
            As[r][c4 + 1] = to_tf32(v.y);
            As[r][c4 + 2] = to_tf32(v.z);
            As[r][c4 + 3] = to_tf32(v.w);
        }
#pragma unroll
        for (int i = tid; i < 32 * 32; i += 256) {
            int r  = i >> 5;
            int c4 = (i & 31) * 4;
            float4 v = *(const float4*)&W[(size_t)(kc + r) * HDIM + c4];
            Ws[r][c4 + 0] = to_tf32(v.x);
            Ws[r][c4 + 1] = to_tf32(v.y);
            Ws[r][c4 + 2] = to_tf32(v.z);
            Ws[r][c4 + 3] = to_tf32(v.w);
        }
        __syncthreads();

#pragma unroll
        for (int ks = 0; ks < 4; ks++) {
            const int k0 = ks * 8;
            uint32_t a[2][4];
#pragma unroll
            for (int mt = 0; mt < 2; mt++) {
                int rb = warp_m + mt * 16;
                a[mt][0] = As[rb + g    ][k0 + c    ];
                a[mt][1] = As[rb + 8 + g][k0 + c    ];
                a[mt][2] = As[rb + g    ][k0 + c + 4];
                a[mt][3] = As[rb + 8 + g][k0 + c + 4];
            }
#pragma unroll
            for (int nt = 0; nt < 8; nt++) {
                int n = warp_n + nt * 8 + g;
                uint32_t b0 = Ws[k0 + c    ][n];
                uint32_t b1 = Ws[k0 + 4 + c][n];
#pragma unroll
                for (int mt = 0; mt < 2; mt++)
                    mma_tf32(acc[mt][nt], a[mt][0], a[mt][1], a[mt][2], a[mt][3], b0, b1);
            }
        }
        __syncthreads();
    }

#pragma unroll
    for (int nt = 0; nt < 8; nt++) {
        int col = warp_n + nt * 8 + 2 * c;
        float2 bb = *(const float2*)&bias[col];
#pragma unroll
        for (int mt = 0; mt < 2; mt++) {
            int row0 = rowBase + warp_m + mt * 16 + g;
            int row1 = row0 + 8;
            if (row0 < M) {
                float2 o;
                o.x = fmaxf(acc[mt][nt][0] + bb.x, 0.f);
                o.y = fmaxf(acc[mt][nt][1] + bb.y, 0.f);
                *(float2*)&C[(size_t)row0 * HDIM + col] = o;
            }
            if (row1 < M) {
                float2 o;
                o.x = fmaxf(acc[mt][nt][2] + bb.x, 0.f);
                o.y = fmaxf(acc[mt][nt][3] + bb.y, 0.f);
                *(float2*)&C[(size_t)row1 * HDIM + col] = o;
            }
        }
    }
}

// ---------------------------------------------------------------------------
// Final zero + pool
// ---------------------------------------------------------------------------
__global__ void zero_kernel(float4* __restrict__ p, size_t n4) {
    size_t i = (size_t)blockIdx.x * blockDim.x + threadIdx.x;
    if (i < n4) p[i] = make_float4(0.f, 0.f, 0.f, 0.f);
}

__global__ void pool_kernel(const float* __restrict__ h,
                            const int* __restrict__ batch,
                            float* __restrict__ out,
                            int M) {
    int warp = (int)(((size_t)blockIdx.x * blockDim.x + threadIdx.x) >> 5);
    int lane = threadIdx.x & 31;
    if (warp >= M) return;
    int g = __ldg(&batch[warp]);
    float4 v = __ldg(((const float4*)(h + (size_t)warp * HDIM)) + lane);
    atomic_add_f4(((float4*)(out + (size_t)g * HDIM)) + lane, v);
}

// ---------------------------------------------------------------------------
// Launch
// ---------------------------------------------------------------------------
extern "C" void kernel_launch(void* const* d_in, const int* in_sizes, int n_in,
                              void* d_out, int out_size) {
    const float* x     = (const float*)d_in[0];
    const int*   ei    = (const int*)d_in[1];
    const int*   batch = (const int*)d_in[2];
    const float* W1[3] = {(const float*)d_in[3], (const float*)d_in[7],  (const float*)d_in[11]};
    const float* b1[3] = {(const float*)d_in[4], (const float*)d_in[8],  (const float*)d_in[12]};
    const float* W2[3] = {(const float*)d_in[5], (const float*)d_in[9],  (const float*)d_in[13]};
    const float* b2[3] = {(const float*)d_in[6], (const float*)d_in[10], (const float*)d_in[14]};

    const int Nn = in_sizes[0] / HDIM;
    const int Ee = in_sizes[1] / 2;
    const int* src = ei;
    const int* dst = ei + Ee;

    float *agg, *zbuf, *h0, *h1;
    int *offs, *cursor, *ssrc;
    cudaGetSymbolAddress((void**)&agg,    g_agg);
    cudaGetSymbolAddress((void**)&zbuf,   g_z);
    cudaGetSymbolAddress((void**)&h0,     g_h0);
    cudaGetSymbolAddress((void**)&h1,     g_h1);
    cudaGetSymbolAddress((void**)&offs,   g_offs);
    cudaGetSymbolAddress((void**)&cursor, g_cursor);
    cudaGetSymbolAddress((void**)&ssrc,   g_ssrc);
    float* hbuf[2] = {h0, h1};

    // --- Build CSR (dst-sorted src list), once per call ---
    zero_int_kernel<<<(Nn + 255) / 256, 256>>>(cursor, Nn);
    hist_kernel<<<(Ee + 255) / 256, 256>>>(dst, cursor, Ee);
    const int C = (Nn + 1023) / 1024;
    scan_kernel<<<1, 1024>>>(cursor, offs, Nn, C);
    permute_kernel<<<(Ee + 255) / 256, 256>>>(src, dst, cursor, ssrc, Ee);

    const int gm_blocks   = (Nn + 127) / 128;
    const int ga_blocks   = (Nn + 7) / 8;
    const int pool_blocks = (Nn + 7) / 8;

    const float* hin = x;
    for (int layer = 0; layer < 3; layer++) {
        float* hout = hbuf[layer & 1];
        gather_kernel<<<ga_blocks, 256>>>(hin, ssrc, offs, agg, Nn);
        gemm_tc_kernel<<<gm_blocks, 256>>>(agg,  W1[layer], b1[layer], zbuf, Nn);
        gemm_tc_kernel<<<gm_blocks, 256>>>(zbuf, W2[layer], b2[layer], hout, Nn);
        hin = hout;
    }

    float* out = (float*)d_out;
    const int zo_blocks = (out_size / 4 + 255) / 256;
    zero_kernel<<<zo_blocks, 256>>>((float4*)out, out_size / 4);
    pool_kernel<<<pool_blocks, 256>>>(hin, batch, out, Nn);
}

// round 7
// speedup vs baseline: 2.2560x; 1.0667x over previous
#include <cuda_runtime.h>
#include <cuda_bf16.h>
#include <cstdint>

#define HDIM 128
#define MAXN 100000
#define MAXE 1600000

// Scratch (device globals; no allocation allowed).
__device__ float g_agg[(size_t)MAXN * HDIM];
__device__ float g_z  [(size_t)MAXN * HDIM];
__device__ float g_h0 [(size_t)MAXN * HDIM];
__device__ float g_h1 [(size_t)MAXN * HDIM];
__device__ int   g_offs[MAXN + 1];
__device__ int   g_cursor[MAXN];
__device__ int   g_ssrc[MAXE];

// Dynamic smem layout for GEMM (floats):
//   As0[128*36] Ws0[32*136] As1[128*36] Ws1[32*136]
#define AS_PITCH 36
#define WS_PITCH 136
#define AS_ELEMS (128 * AS_PITCH)
#define WS_ELEMS (32 * WS_PITCH)
#define GEMM_SMEM_BYTES ((AS_ELEMS + WS_ELEMS) * 2 * 4)

// ---------------------------------------------------------------------------
// Helpers
// ---------------------------------------------------------------------------
__device__ __forceinline__ void atomic_add_f4(float4* addr, float4 v) {
#if __CUDA_ARCH__ >= 900
    atomicAdd(addr, v);
#else
    float* f = (float*)addr;
    atomicAdd(f + 0, v.x); atomicAdd(f + 1, v.y);
    atomicAdd(f + 2, v.z); atomicAdd(f + 3, v.w);
#endif
}

__device__ __forceinline__ uint32_t to_tf32(float x) {
    uint32_t r;
    asm("cvt.rna.tf32.f32 %0, %1;" : "=r"(r) : "f"(x));
    return r;
}

__device__ __forceinline__ void mma_tf32(float d[4],
                                         uint32_t a0, uint32_t a1, uint32_t a2, uint32_t a3,
                                         uint32_t b0, uint32_t b1) {
    asm volatile(
        "mma.sync.aligned.m16n8k8.row.col.f32.tf32.tf32.f32 "
        "{%0,%1,%2,%3}, {%4,%5,%6,%7}, {%8,%9}, {%0,%1,%2,%3};\n"
        : "+f"(d[0]), "+f"(d[1]), "+f"(d[2]), "+f"(d[3])
        : "r"(a0), "r"(a1), "r"(a2), "r"(a3), "r"(b0), "r"(b1));
}

__device__ __forceinline__ uint32_t smem_u32(const void* p) {
    return (uint32_t)__cvta_generic_to_shared(p);
}

__device__ __forceinline__ void cp_async16(uint32_t saddr, const void* gptr) {
    asm volatile("cp.async.cg.shared.global [%0], [%1], 16;\n" :: "r"(saddr), "l"(gptr));
}
__device__ __forceinline__ void cp_commit() {
    asm volatile("cp.async.commit_group;\n");
}
template <int N>
__device__ __forceinline__ void cp_wait() {
    asm volatile("cp.async.wait_group %0;\n" :: "n"(N));
}

// ---------------------------------------------------------------------------
// CSR build kernels
// ---------------------------------------------------------------------------
__global__ void zero_int_kernel(int* __restrict__ p, int n) {
    int i = blockIdx.x * blockDim.x + threadIdx.x;
    if (i < n) p[i] = 0;
}

__global__ void hist_kernel(const int* __restrict__ dst, int* __restrict__ count, int E) {
    int e = blockIdx.x * blockDim.x + threadIdx.x;
    if (e < E) atomicAdd(&count[__ldg(&dst[e])], 1);
}

__global__ __launch_bounds__(1024) void scan_kernel(int* __restrict__ cnt,
                                                    int* __restrict__ offs,
                                                    int N, int C) {
    __shared__ int part[1024];
    const int t = threadIdx.x;
    const int beg = min(t * C, N);
    const int end = min(beg + C, N);
    int s = 0;
    for (int i = beg; i < end; i++) s += cnt[i];
    part[t] = s;
    __syncthreads();
    for (int d = 1; d < 1024; d <<= 1) {
        int val = (t >= d) ? part[t - d] : 0;
        __syncthreads();
        if (t >= d) part[t] += val;
        __syncthreads();
    }
    int run = (t == 0) ? 0 : part[t - 1];
    for (int i = beg; i < end; i++) {
        int c = cnt[i];
        offs[i] = run;
        cnt[i]  = run;
        run += c;
    }
    if (t == 1023) offs[N] = part[1023];
}

__global__ void permute_kernel(const int* __restrict__ src,
                               const int* __restrict__ dst,
                               int* __restrict__ cursor,
                               int* __restrict__ ssrc, int E) {
    int e = blockIdx.x * blockDim.x + threadIdx.x;
    if (e >= E) return;
    int d = __ldg(&dst[e]);
    int pos = atomicAdd(&cursor[d], 1);
    ssrc[pos] = __ldg(&src[e]);
}

// ---------------------------------------------------------------------------
// Gather: agg[n,:] = h[n,:] + sum_{e: dst==n} h[src[e],:]
// ---------------------------------------------------------------------------
__global__ __launch_bounds__(256) void gather_kernel(const float* __restrict__ h,
                                                     const int* __restrict__ ssrc,
                                                     const int* __restrict__ offs,
                                                     float* __restrict__ agg,
                                                     int N) {
    int node = (int)(((size_t)blockIdx.x * blockDim.x + threadIdx.x) >> 5);
    int lane = threadIdx.x & 31;
    if (node >= N) return;
    const float4* hb = (const float4*)h;
    int beg = __ldg(&offs[node]);
    int end = __ldg(&offs[node + 1]);

    float4 v0 = __ldg(hb + (size_t)node * 32 + lane);
    float4 v1 = make_float4(0.f, 0.f, 0.f, 0.f);
    int i = beg;
    for (; i + 1 < end; i += 2) {
        int s0 = __ldg(&ssrc[i]);
        int s1 = __ldg(&ssrc[i + 1]);
        float4 a = __ldg(hb + (size_t)s0 * 32 + lane);
        float4 b = __ldg(hb + (size_t)s1 * 32 + lane);
        v0.x += a.x; v0.y += a.y; v0.z += a.z; v0.w += a.w;
        v1.x += b.x; v1.y += b.y; v1.z += b.z; v1.w += b.w;
    }
    if (i < end) {
        int s0 = __ldg(&ssrc[i]);
        float4 a = __ldg(hb + (size_t)s0 * 32 + lane);
        v0.x += a.x; v0.y += a.y; v0.z += a.z; v0.w += a.w;
    }
    v0.x += v1.x; v0.y += v1.y; v0.z += v1.z; v0.w += v1.w;
    ((float4*)agg)[(size_t)node * 32 + lane] = v0;
}

// ---------------------------------------------------------------------------
// Tensor-core GEMM with cp.async double buffering.
// C[M,128] = relu( A @ W + b ). Raw fp32 staged in smem; cvt.rna at fragment
// build (numerics identical to round-3 kernel). Ws pitch 136 -> conflict-free
// B-fragment loads (bank = 8c + g).
// ---------------------------------------------------------------------------
__device__ __forceinline__ void gemm_load_stage(
    const float* __restrict__ A, const float* __restrict__ W,
    float* As, float* Ws, int rowBase, int kc, int M, int tid) {
    // A chunk: 128 rows x 32 floats = 1024 float4
#pragma unroll
    for (int i = tid; i < 1024; i += 256) {
        int r  = i >> 3;
        int c4 = (i & 7) * 4;
        int gr = rowBase + r;
        float* dst = &As[r * AS_PITCH + c4];
        if (gr < M) {
            cp_async16(smem_u32(dst), &A[(size_t)gr * HDIM + kc + c4]);
        } else {
            *(float4*)dst = make_float4(0.f, 0.f, 0.f, 0.f);
        }
    }
    // W chunk: 32 rows x 128 floats = 1024 float4
#pragma unroll
    for (int i = tid; i < 1024; i += 256) {
        int r  = i >> 5;
        int c4 = (i & 31) * 4;
        cp_async16(smem_u32(&Ws[r * WS_PITCH + c4]), &W[(size_t)(kc + r) * HDIM + c4]);
    }
}

__global__ __launch_bounds__(256) void gemm_tc_kernel(
    const float* __restrict__ A,
    const float* __restrict__ W,
    const float* __restrict__ bias,
    float* __restrict__ C,
    int M) {
    extern __shared__ float smem[];
    float* Asb[2] = {smem, smem + AS_ELEMS + WS_ELEMS};
    float* Wsb[2] = {smem + AS_ELEMS, smem + 2 * AS_ELEMS + WS_ELEMS};

    const int tid  = threadIdx.x;
    const int lane = tid & 31;
    const int wid  = tid >> 5;
    const int warp_m = (wid & 3) * 32;
    const int warp_n = (wid >> 2) * 64;
    const int g = lane >> 2;
    const int c = lane & 3;
    const int rowBase = blockIdx.x * 128;

    float acc[2][8][4];
#pragma unroll
    for (int mt = 0; mt < 2; mt++)
#pragma unroll
        for (int nt = 0; nt < 8; nt++)
#pragma unroll
            for (int j = 0; j < 4; j++) acc[mt][nt][j] = 0.f;

    // Prologue: stage 0
    gemm_load_stage(A, W, Asb[0], Wsb[0], rowBase, 0, M, tid);
    cp_commit();

#pragma unroll
    for (int ci = 0; ci < 4; ci++) {
        if (ci < 3) {
            gemm_load_stage(A, W, Asb[(ci + 1) & 1], Wsb[(ci + 1) & 1],
                            rowBase, (ci + 1) * 32, M, tid);
            cp_commit();
            cp_wait<1>();   // current stage complete, next in flight
        } else {
            cp_wait<0>();
        }
        __syncthreads();

        const float* As = Asb[ci & 1];
        const float* Ws = Wsb[ci & 1];
#pragma unroll
        for (int ks = 0; ks < 4; ks++) {
            const int k0 = ks * 8;
            uint32_t a[2][4];
#pragma unroll
            for (int mt = 0; mt < 2; mt++) {
                int rb = warp_m + mt * 16;
                a[mt][0] = to_tf32(As[(rb + g    ) * AS_PITCH + k0 + c    ]);
                a[mt][1] = to_tf32(As[(rb + 8 + g) * AS_PITCH + k0 + c    ]);
                a[mt][2] = to_tf32(As[(rb + g    ) * AS_PITCH + k0 + c + 4]);
                a[mt][3] = to_tf32(As[(rb + 8 + g) * AS_PITCH + k0 + c + 4]);
            }
#pragma unroll
            for (int nt = 0; nt < 8; nt++) {
                int n = warp_n + nt * 8 + g;
                uint32_t b0 = to_tf32(Ws[(k0 + c    ) * WS_PITCH + n]);
                uint32_t b1 = to_tf32(Ws[(k0 + 4 + c) * WS_PITCH + n]);
#pragma unroll
                for (int mt = 0; mt < 2; mt++)
                    mma_tf32(acc[mt][nt], a[mt][0], a[mt][1], a[mt][2], a[mt][3], b0, b1);
            }
        }
        __syncthreads();
    }

    // Epilogue: bias + relu
#pragma unroll
    for (int nt = 0; nt < 8; nt++) {
        int col = warp_n + nt * 8 + 2 * c;
        float2 bb = *(const float2*)&bias[col];
#pragma unroll
        for (int mt = 0; mt < 2; mt++) {
            int row0 = rowBase + warp_m + mt * 16 + g;
            int row1 = row0 + 8;
            if (row0 < M) {
                float2 o;
                o.x = fmaxf(acc[mt][nt][0] + bb.x, 0.f);
                o.y = fmaxf(acc[mt][nt][1] + bb.y, 0.f);
                *(float2*)&C[(size_t)row0 * HDIM + col] = o;
            }
            if (row1 < M) {
                float2 o;
                o.x = fmaxf(acc[mt][nt][2] + bb.x, 0.f);
                o.y = fmaxf(acc[mt][nt][3] + bb.y, 0.f);
                *(float2*)&C[(size_t)row1 * HDIM + col] = o;
            }
        }
    }
}

// ---------------------------------------------------------------------------
// Final zero + pool
// ---------------------------------------------------------------------------
__global__ void zero_kernel(float4* __restrict__ p, size_t n4) {
    size_t i = (size_t)blockIdx.x * blockDim.x + threadIdx.x;
    if (i < n4) p[i] = make_float4(0.f, 0.f, 0.f, 0.f);
}

__global__ void pool_kernel(const float* __restrict__ h,
                            const int* __restrict__ batch,
                            float* __restrict__ out,
                            int M) {
    int warp = (int)(((size_t)blockIdx.x * blockDim.x + threadIdx.x) >> 5);
    int lane = threadIdx.x & 31;
    if (warp >= M) return;
    int g = __ldg(&batch[warp]);
    float4 v = __ldg(((const float4*)(h + (size_t)warp * HDIM)) + lane);
    atomic_add_f4(((float4*)(out + (size_t)g * HDIM)) + lane, v);
}

// ---------------------------------------------------------------------------
// Launch
// ---------------------------------------------------------------------------
extern "C" void kernel_launch(void* const* d_in, const int* in_sizes, int n_in,
                              void* d_out, int out_size) {
    const float* x     = (const float*)d_in[0];
    const int*   ei    = (const int*)d_in[1];
    const int*   batch = (const int*)d_in[2];
    const float* W1[3] = {(const float*)d_in[3], (const float*)d_in[7],  (const float*)d_in[11]};
    const float* b1[3] = {(const float*)d_in[4], (const float*)d_in[8],  (const float*)d_in[12]};
    const float* W2[3] = {(const float*)d_in[5], (const float*)d_in[9],  (const float*)d_in[13]};
    const float* b2[3] = {(const float*)d_in[6], (const float*)d_in[10], (const float*)d_in[14]};

    const int Nn = in_sizes[0] / HDIM;
    const int Ee = in_sizes[1] / 2;
    const int* src = ei;
    const int* dst = ei + Ee;

    float *agg, *zbuf, *h0, *h1;
    int *offs, *cursor, *ssrc;
    cudaGetSymbolAddress((void**)&agg,    g_agg);
    cudaGetSymbolAddress((void**)&zbuf,   g_z);
    cudaGetSymbolAddress((void**)&h0,     g_h0);
    cudaGetSymbolAddress((void**)&h1,     g_h1);
    cudaGetSymbolAddress((void**)&offs,   g_offs);
    cudaGetSymbolAddress((void**)&cursor, g_cursor);
    cudaGetSymbolAddress((void**)&ssrc,   g_ssrc);
    float* hbuf[2] = {h0, h1};

    cudaFuncSetAttribute(gemm_tc_kernel,
                         cudaFuncAttributeMaxDynamicSharedMemorySize, GEMM_SMEM_BYTES);

    // --- Build CSR (dst-sorted src list), once per call ---
    zero_int_kernel<<<(Nn + 255) / 256, 256>>>(cursor, Nn);
    hist_kernel<<<(Ee + 255) / 256, 256>>>(dst, cursor, Ee);
    const int C = (Nn + 1023) / 1024;
    scan_kernel<<<1, 1024>>>(cursor, offs, Nn, C);
    permute_kernel<<<(Ee + 255) / 256, 256>>>(src, dst, cursor, ssrc, Ee);

    const int gm_blocks   = (Nn + 127) / 128;
    const int ga_blocks   = (Nn + 7) / 8;
    const int pool_blocks = (Nn + 7) / 8;

    const float* hin = x;
    for (int layer = 0; layer < 3; layer++) {
        float* hout = hbuf[layer & 1];
        gather_kernel<<<ga_blocks, 256>>>(hin, ssrc, offs, agg, Nn);
        gemm_tc_kernel<<<gm_blocks, 256, GEMM_SMEM_BYTES>>>(agg,  W1[layer], b1[layer], zbuf, Nn);
        gemm_tc_kernel<<<gm_blocks, 256, GEMM_SMEM_BYTES>>>(zbuf, W2[layer], b2[layer], hout, Nn);
        hin = hout;
    }

    float* out = (float*)d_out;
    const int zo_blocks = (out_size / 4 + 255) / 256;
    zero_kernel<<<zo_blocks, 256>>>((float4*)out, out_size / 4);
    pool_kernel<<<pool_blocks, 256>>>(hin, batch, out, Nn);
}